// round 5
// baseline (speedup 1.0000x reference)
#include <cuda_runtime.h>
#include <cstddef>

#define BB    2
#define NN    207
#define TT    12
#define FIN   64
#define HH    8
#define CDIM  8
#define HSTRIDE 12        // padded row stride (floats): 48B, conflict-free LDS.128
#define NWORDS 7          // ceil(207/32)
#define NCHUNK 3
#define RPC   69          // rows per chunk: 207 = 3*69
#define RPG   3           // rows per warp-group iteration
#define NGRP  23          // 69/3, perfectly balanced over 8 warps

// ---------------------------------------------------------------------------
// One fused kernel. grid = B*T*H*NCHUNK = 576, block = 256 (8 warps).
// leaky_0.2(x) = 0.6x + 0.4|x|  =>
// e[n,m] = p_n + p_m + sum_c (0.4 a_c)|h_n_c + h_m_c|,  p = sum_c 0.6 a_c h_c.
// No-max softmax (scores are O(10), exp cannot overflow fp32).
// ---------------------------------------------------------------------------
__global__ void __launch_bounds__(256) k_fused(
    const float* __restrict__ X, const float* __restrict__ A,
    const float* __restrict__ W, const float* __restrict__ a_vec,
    float* __restrict__ out)
{
    __shared__ float    h_rm[NN * HSTRIDE];   // row-major h, 9.9 KB
    __shared__ float    p_sh[NN + 1];
    __shared__ unsigned msk[RPC * NWORDS];    // this chunk's adjacency bits
    __shared__ float    ws[FIN * CDIM];       // W column block for this head

    int bx    = blockIdx.x;
    int bth   = bx / NCHUNK;                  // (b*T+t)*H + hd
    int chunk = bx - bth * NCHUNK;
    int hd    = bth & 7;
    int bt    = bth >> 3;
    int t     = bt % TT;
    int b     = bt / TT;
    int tid   = threadIdx.x;
    int warp  = tid >> 5, lane = tid & 31;
    int n0    = chunk * RPC;

    float a4[CDIM];
#pragma unroll
    for (int c = 0; c < CDIM; c++) a4[c] = 0.4f * __ldg(&a_vec[c]);

    // ---- adjacency bitmask for this chunk's 69 rows (ballot per 32-col word)
    for (int p = warp; p < RPC * NWORDS; p += 8) {
        int row = p / NWORDS, k = p - row * NWORDS;
        int m = k * 32 + lane;
        bool v = (m < NN) && (A[(n0 + row) * NN + m] > 0.0f);
        unsigned bits = __ballot_sync(0xffffffffu, v);
        if (lane == 0) msk[p] = bits;
    }

    // ---- stage W[:, hd*8 .. hd*8+7]
    if (tid < 128) {
        int f = tid >> 1, half = tid & 1;
        *(float4*)&ws[f * CDIM + half * 4] =
            *(const float4*)&W[f * 64 + hd * CDIM + half * 4];
    }
    __syncthreads();

    // ---- per-block GEMM: thread n computes h[n][0..7]
    if (tid < NN) {
        int n = tid;
        const float* xr = X + ((size_t)(b * NN + n) * TT + t) * FIN;
        float acc[CDIM];
#pragma unroll
        for (int c = 0; c < CDIM; c++) acc[c] = 0.0f;
#pragma unroll
        for (int f = 0; f < FIN; f += 4) {
            float4 xv = *(const float4*)(xr + f);
            float xs4[4] = {xv.x, xv.y, xv.z, xv.w};
#pragma unroll
            for (int ff = 0; ff < 4; ff++) {
                float xs = xs4[ff];
                float4 w0 = *(float4*)&ws[(f + ff) * CDIM];
                float4 w1 = *(float4*)&ws[(f + ff) * CDIM + 4];
                acc[0] = fmaf(xs, w0.x, acc[0]);
                acc[1] = fmaf(xs, w0.y, acc[1]);
                acc[2] = fmaf(xs, w0.z, acc[2]);
                acc[3] = fmaf(xs, w0.w, acc[3]);
                acc[4] = fmaf(xs, w1.x, acc[4]);
                acc[5] = fmaf(xs, w1.y, acc[5]);
                acc[6] = fmaf(xs, w1.z, acc[6]);
                acc[7] = fmaf(xs, w1.w, acc[7]);
            }
        }
        float p = 0.0f;
#pragma unroll
        for (int c = 0; c < CDIM; c++) {
            h_rm[n * HSTRIDE + c] = acc[c];
            p = fmaf(1.5f * a4[c], acc[c], p);    // 0.6 a_c = 1.5 * (0.4 a_c)
        }
        p_sh[n] = p;
    }
    __syncthreads();

    // ---- attention: 23 groups x 3 rows, one group per warp per iteration
    for (int g = warp; g < NGRP; g += 8) {
        int rl0 = g * RPG;          // local row base
        int r0  = n0 + rl0;         // global row base

        float hn[RPG][CDIM], pn[RPG], s[RPG];
#pragma unroll
        for (int j = 0; j < RPG; j++) {
            float4 u0 = *(float4*)&h_rm[(r0 + j) * HSTRIDE];
            float4 u1 = *(float4*)&h_rm[(r0 + j) * HSTRIDE + 4];
            hn[j][0] = u0.x; hn[j][1] = u0.y; hn[j][2] = u0.z; hn[j][3] = u0.w;
            hn[j][4] = u1.x; hn[j][5] = u1.y; hn[j][6] = u1.z; hn[j][7] = u1.w;
            pn[j] = p_sh[r0 + j];
            s[j]  = 0.0f;
        }

#pragma unroll
        for (int k = 0; k < NWORDS; k++) {
            int m  = k * 32 + lane;
            int mm = min(m, NN - 1);
            float4 m0 = *(float4*)&h_rm[mm * HSTRIDE];
            float4 m1 = *(float4*)&h_rm[mm * HSTRIDE + 4];
            float hm[CDIM] = {m0.x, m0.y, m0.z, m0.w, m1.x, m1.y, m1.z, m1.w};
            float pm = p_sh[mm];
#pragma unroll
            for (int j = 0; j < RPG; j++) {
                float q0 = 0.f, q1 = 0.f;
#pragma unroll
                for (int c = 0; c < CDIM; c++) {
                    float x = hn[j][c] + hm[c];
                    if (c & 1) q1 = fmaf(a4[c], fabsf(x), q1);
                    else       q0 = fmaf(a4[c], fabsf(x), q0);
                }
                float ev = pn[j] + pm + (q0 + q1);
                unsigned bits = msk[(rl0 + j) * NWORDS + k];   // broadcast LDS
                float ex = __expf(ev);
                s[j] += ((bits >> lane) & 1u) ? ex : 0.0f;
            }
        }

        // normalizers (no max pass needed)
#pragma unroll
        for (int off = 16; off; off >>= 1) {
#pragma unroll
            for (int j = 0; j < RPG; j++)
                s[j] += __shfl_xor_sync(0xffffffffu, s[j], off);
        }

        // diagonal + output
#pragma unroll
        for (int j = 0; j < RPG; j++) {
            int n = r0 + j;
            float d = 0.0f;
#pragma unroll
            for (int c = 0; c < CDIM; c++) d = fmaf(a4[c], fabsf(hn[j][c]), d);
            float enn = 2.0f * (pn[j] + d);
            unsigned db = msk[(rl0 + j) * NWORDS + (n >> 5)];
            float att = ((db >> (n & 31)) & 1u)
                        ? __fdividef(__expf(enn), s[j]) : 0.0f;
            if (lane < CDIM)
                out[((size_t)(b * NN + n) * TT + t) * (HH * CDIM) + hd * CDIM + lane]
                    = att * h_rm[n * HSTRIDE + lane];
        }
    }
}

// ---------------------------------------------------------------------------
extern "C" void kernel_launch(void* const* d_in, const int* in_sizes, int n_in,
                              void* d_out, int out_size) {
    const float* X  = (const float*)d_in[0];   // (2,207,12,64)
    const float* A  = (const float*)d_in[1];   // (207,207)
    const float* W  = (const float*)d_in[2];   // (64,64)
    const float* av = (const float*)d_in[3];   // (8,)
    float* out = (float*)d_out;                // (2,207,12,64)

    k_fused<<<BB * TT * HH * NCHUNK, 256>>>(X, A, W, av, out);
}